// round 14
// baseline (speedup 1.0000x reference)
#include <cuda_runtime.h>
#include <math.h>

#define NMAX   8192
#define KMAX   64
#define NBINS  1024
#define NB     64        // blocks (all co-resident: 64 < 148 SMs)
#define BLK    1024
#define TSUB   8         // threads per j
#define JB     (BLK / TSUB)   // 128 j's per block

// Scratch (__device__ globals: allocation-free rule; zero-initialized)
__device__ float    g_xs[NMAX];          // bin-sorted x, exp2-domain scaled
__device__ float    g_xo[NMAX];          // bin-sorted x, original
__device__ int      g_cnt[NBINS];        // histogram   (re-zeroed in phase 4)
__device__ int      g_off[NBINS];        // scatter off (re-zeroed in phase 4)
__device__ unsigned g_bar;               // monotone barrier counter
__device__ unsigned g_epoch[NB];         // per-block barrier epoch (monotone)

__device__ __forceinline__ float ex2f(float e) {
    float r;
    asm("ex2.approx.ftz.f32 %0, %1;" : "=f"(r) : "f"(e));
    return r;
}

// Grid barrier: release-reduction arrive (REDG) + acquire spin by thread 0.
// MUST be called uniformly by all threads of all blocks (contains barriers).
__device__ __forceinline__ void gridbar(unsigned goal) {
    __syncthreads();
    if (threadIdx.x == 0) {
        asm volatile("red.release.gpu.global.add.u32 [%0], %1;"
                     :: "l"(&g_bar), "r"(1u) : "memory");
        unsigned v;
        do {
            asm volatile("ld.acquire.gpu.global.u32 %0, [%1];" : "=r"(v) : "l"(&g_bar));
        } while (v < goal);
    }
    __syncthreads();
}

__global__ void __launch_bounds__(BLK, 1)
k_fused(const float* __restrict__ x,
        const float* __restrict__ wl,
        const float* __restrict__ means,
        const float* __restrict__ lv,
        float* __restrict__ out,
        int n, int K, float scaleS, float invC) {
    __shared__ float    cA[KMAX], cB[KMAX], mu[KMAX];
    __shared__ int      binstart[NBINS + 1];
    __shared__ int      wsum[32];
    __shared__ float    sred[32];
    __shared__ unsigned s_ep;
    int t = threadIdx.x, lane = t & 31, wid = t >> 5;
    int b = blockIdx.x;
    unsigned nb = gridDim.x;

    const float RLO  = -8.0f;                  // fixed bin range [-8, 8]
    const float INVW = (float)NBINS / 16.0f;

    // broadcast this block's barrier epoch so every thread can compute goals
    if (t == 0) s_ep = g_epoch[b];
    if (b == 0 && t == 0) *out = 0.0f;
    __syncthreads();
    unsigned ep = s_ep;

    // ---- phase 1: histogram of this block's slice ----
    int sl  = (n + (int)nb - 1) / (int)nb;     // 128 for n=8192
    int i0s = b * sl;
    int i1s = min(n, i0s + sl);
    for (int i = i0s + t; i < i1s; i += BLK) {
        int bin = min(NBINS - 1, max(0, (int)((x[i] - RLO) * INVW)));
        atomicAdd(&g_cnt[bin], 1);
    }
    gridbar((ep + 1u) * nb);                   // uniform call — all threads

    // ---- phase 2: every block redundantly scans the histogram into smem ----
    {
        int c = g_cnt[t];                      // NBINS == BLK
        int incl = c;
#pragma unroll
        for (int o = 1; o < 32; o <<= 1) {
            int v = __shfl_up_sync(~0u, incl, o);
            if (lane >= o) incl += v;
        }
        if (lane == 31) wsum[wid] = incl;
        __syncthreads();
        if (wid == 0) {
            int v = wsum[lane];
#pragma unroll
            for (int o = 1; o < 32; o <<= 1) {
                int u = __shfl_up_sync(~0u, v, o);
                if (lane >= o) v += u;
            }
            wsum[lane] = v;
        }
        __syncthreads();
        int base = incl - c + ((wid > 0) ? wsum[wid - 1] : 0);
        binstart[t] = base;
        if (t == BLK - 1) binstart[NBINS] = base + c;    // == n
        __syncthreads();
    }

    // ---- phase 3: scatter (counting sort) ----
    for (int i = i0s + t; i < i1s; i += BLK) {
        float xv = x[i];
        int bin = min(NBINS - 1, max(0, (int)((xv - RLO) * INVW)));
        int pos = binstart[bin] + atomicAdd(&g_off[bin], 1);
        g_xs[pos] = xv * scaleS;
        g_xo[pos] = xv;
    }

    // ---- softmax prep: single warp, K<=64 (overlaps other blocks' phase 3) ----
    if (wid == 0) {
        int k0 = lane, k1 = lane + 32;
        float w0 = (k0 < K) ? wl[k0] : -INFINITY;
        float w1 = (k1 < K) ? wl[k1] : -INFINITY;
        float m = fmaxf(w0, w1);
#pragma unroll
        for (int o = 16; o; o >>= 1) m = fmaxf(m, __shfl_xor_sync(~0u, m, o));
        float e0 = (k0 < K) ? __expf(w0 - m) : 0.0f;
        float e1 = (k1 < K) ? __expf(w1 - m) : 0.0f;
        float s = e0 + e1;
#pragma unroll
        for (int o = 16; o; o >>= 1) s += __shfl_xor_sync(~0u, s, o);
        float inv_s = 1.0f / s;
        if (k0 < K) {
            float var = __expf(lv[k0]);
            cA[k0] = e0 * inv_s * rsqrtf(2.0f * (float)M_PI * var);
            cB[k0] = -0.5f / var;
            mu[k0] = means[k0];
        }
        if (k1 < K) {
            float var = __expf(lv[k1]);
            cA[k1] = e1 * inv_s * rsqrtf(2.0f * (float)M_PI * var);
            cB[k1] = -0.5f / var;
            mu[k1] = means[k1];
        }
    }

    gridbar((ep + 2u) * nb);                   // uniform call — all threads

    // ---- phase 4: windowed KDE + mixture pdf + reduction + cleanup ----
    if (t == 0) g_epoch[b] = ep + 2u;          // advance epoch for next replay
    // re-zero scratch for the next graph replay (all uses finished)
    if (t < NBINS / NB) {
        g_cnt[b * (NBINS / NB) + t] = 0;
        g_off[b * (NBINS / NB) + t] = 0;
    }

    int jl = t / TSUB, ts = t & (TSUB - 1);
    int j  = b * JB + jl;

    float kde = 0.0f, mix = 0.0f;
    if (j < n) {
        float xs    = g_xs[j];
        float minS  = RLO * scaleS;
        float invwS = INVW / scaleS;
        const float RS = 6.5f;                 // dropped terms < 2^-42

        int lo = min(NBINS - 1, max(0, (int)((xs - RS - minS) * invwS)));
        int hi = min(NBINS - 1, max(0, (int)((xs + RS - minS) * invwS)));
        int i0 = binstart[lo];
        int i1 = binstart[hi + 1];

        float k0 = 0.0f, k1 = 0.0f;
        int i = i0 + ts;
        for (; i + TSUB < i1; i += 2 * TSUB) {
            float d0 = xs - g_xs[i];
            float d1 = xs - g_xs[i + TSUB];
            k0 += ex2f(-d0 * d0);
            k1 += ex2f(-d1 * d1);
        }
        if (i < i1) {
            float d = xs - g_xs[i];
            k0 += ex2f(-d * d);
        }
        kde = k0 + k1;

        float xo = g_xo[j];
        for (int k = ts; k < K; k += TSUB) {
            float d = xo - mu[k];
            mix += cA[k] * __expf(cB[k] * d * d);
        }
    }

    // combine the TSUB cooperating lanes
#pragma unroll
    for (int o = 1; o < TSUB; o <<= 1) {
        kde += __shfl_xor_sync(~0u, kde, o);
        mix += __shfl_xor_sync(~0u, mix, o);
    }

    float val = 0.0f;
    if (j < n && ts == 0) {
        float err = mix - kde * invC;
        val = err * err;
    }
#pragma unroll
    for (int o = 16; o; o >>= 1) val += __shfl_xor_sync(~0u, val, o);
    if (lane == 0) sred[wid] = val;
    __syncthreads();
    if (wid == 0) {
        float v = sred[lane];
#pragma unroll
        for (int o = 16; o; o >>= 1) v += __shfl_xor_sync(~0u, v, o);
        if (lane == 0) atomicAdd(out, v);
    }
}

// ---------------------------------------------------------------------------
extern "C" void kernel_launch(void* const* d_in, const int* in_sizes, int n_in,
                              void* d_out, int out_size) {
    const float* x     = (const float*)d_in[0];
    const float* wl    = (const float*)d_in[1];
    const float* means = (const float*)d_in[2];
    const float* lv    = (const float*)d_in[3];
    float* out = (float*)d_out;

    int n = in_sizes[0];   // 8192
    int K = in_sizes[1];   // 64

    // bandwidth = 0.5 * 128 / n  (= 2^-7 for n = 8192)
    double bw    = 64.0 / (double)n;
    double bw2   = bw * bw;
    double Ckde  = -0.5 / bw2;
    double LOG2E = 1.4426950408889634;
    float  scaleS = (float)sqrt(-Ckde * LOG2E);   // exp2-domain prescale
    float  invC   = (float)(1.0 / (sqrt(2.0 * M_PI * bw2) * (double)n));

    k_fused<<<NB, BLK>>>(x, wl, means, lv, out, n, K, scaleS, invC);
}

// round 15
// speedup vs baseline: 1.6200x; 1.6200x over previous
#include <cuda_runtime.h>
#include <math.h>

#define NMAX   8192
#define KMAX   64
#define NBINS  1024
#define NB     128       // blocks (all co-resident: 128 < 148 SMs)
#define BLK    512
#define TSUB   8         // threads per j
#define JB     (BLK / TSUB)   // 64 j's per block

// Scratch (__device__ globals: allocation-free rule; zero-initialized)
__device__ float    g_xs[NMAX];          // bin-sorted x, exp2-domain scaled
__device__ float    g_xo[NMAX];          // bin-sorted x, original
__device__ int      g_cnt[NBINS];        // histogram (re-zeroed in phase 4)
__device__ unsigned g_bar;               // monotone barrier counter
__device__ unsigned g_epoch[NB];         // per-block barrier epoch (monotone)

__device__ __forceinline__ float ex2f(float e) {
    float r;
    asm("ex2.approx.ftz.f32 %0, %1;" : "=f"(r) : "f"(e));
    return r;
}

// Grid barrier: release-reduction arrive (REDG) + acquire spin by thread 0.
// MUST be called uniformly by all threads of all blocks.
__device__ __forceinline__ void gridbar(unsigned goal) {
    __syncthreads();
    if (threadIdx.x == 0) {
        asm volatile("red.release.gpu.global.add.u32 [%0], %1;"
                     :: "l"(&g_bar), "r"(1u) : "memory");
        unsigned v;
        do {
            asm volatile("ld.acquire.gpu.global.u32 %0, [%1];" : "=r"(v) : "l"(&g_bar));
        } while (v < goal);
    }
    __syncthreads();
}

__global__ void __launch_bounds__(BLK, 1)
k_fused(const float* __restrict__ x,
        const float* __restrict__ wl,
        const float* __restrict__ means,
        const float* __restrict__ lv,
        float* __restrict__ out,
        int n, int K, float scaleS, float invC) {
    __shared__ float    cA[KMAX], cB2[KMAX], mu[KMAX];  // cB2 = log2e-scaled
    __shared__ int      binstart[NBINS + 1];
    __shared__ int      wsum[16];
    __shared__ float    sred[16];
    __shared__ unsigned s_ep;
    int t = threadIdx.x, lane = t & 31, wid = t >> 5;
    int b = blockIdx.x;
    unsigned nb = gridDim.x;

    const float RLO  = -8.0f;                 // fixed bin range [-8, 8]
    const float INVW = (float)NBINS / 16.0f;
    const float L2E  = 1.44269504f;

    if (t == 0) s_ep = g_epoch[b];
    if (b == 0 && t == 0) *out = 0.0f;
    __syncthreads();
    unsigned ep = s_ep;

    // ---- phase 1: histogram of this block's slice; keep (val,bin,pos) in regs ----
    int sl  = (n + (int)nb - 1) / (int)nb;    // 64 for n=8192, nb=128
    int i0s = b * sl;
    int i1s = min(n, i0s + sl);
    float myv = 0.0f; int mybin = -1, mypos = 0;   // each thread holds <=1 element
    {
        int i = i0s + t;                      // sl (64) <= BLK (512): single step
        if (i < i1s) {
            myv = x[i];
            mybin = min(NBINS - 1, max(0, (int)((myv - RLO) * INVW)));
            mypos = atomicAdd(&g_cnt[mybin], 1);
        }
    }
    gridbar((ep + 1u) * nb);

    // ---- phase 2: redundant per-block scan of histogram (2 bins/thread) ----
    {
        int c0 = g_cnt[2 * t], c1 = g_cnt[2 * t + 1];
        int loc = c0 + c1;
        int incl = loc;
#pragma unroll
        for (int o = 1; o < 32; o <<= 1) {
            int v = __shfl_up_sync(~0u, incl, o);
            if (lane >= o) incl += v;
        }
        if (lane == 31) wsum[wid] = incl;
        __syncthreads();
        if (wid == 0 && lane < 16) {
            int v = wsum[lane];
#pragma unroll
            for (int o = 1; o < 16; o <<= 1) {
                int u = __shfl_up_sync(0xffffu, v, o);
                if (lane >= o) v += u;
            }
            wsum[lane] = v;
        }
        __syncthreads();
        int base = incl - loc + ((wid > 0) ? wsum[wid - 1] : 0);
        binstart[2 * t]     = base;
        binstart[2 * t + 1] = base + c0;
        if (t == BLK - 1) binstart[NBINS] = base + loc;    // == n
        __syncthreads();
    }

    // ---- phase 3: scatter (plain stores; pos captured in phase 1) ----
    if (mybin >= 0) {
        int pos = binstart[mybin] + mypos;
        g_xs[pos] = myv * scaleS;
        g_xo[pos] = myv;
    }

    // ---- softmax prep: single warp (overlaps other blocks' phases) ----
    if (wid == 0) {
        int k0 = lane, k1 = lane + 32;
        float w0 = (k0 < K) ? wl[k0] : -INFINITY;
        float w1 = (k1 < K) ? wl[k1] : -INFINITY;
        float m = fmaxf(w0, w1);
#pragma unroll
        for (int o = 16; o; o >>= 1) m = fmaxf(m, __shfl_xor_sync(~0u, m, o));
        float e0 = (k0 < K) ? __expf(w0 - m) : 0.0f;
        float e1 = (k1 < K) ? __expf(w1 - m) : 0.0f;
        float s = e0 + e1;
#pragma unroll
        for (int o = 16; o; o >>= 1) s += __shfl_xor_sync(~0u, s, o);
        float inv_s = 1.0f / s;
        if (k0 < K) {
            float var = __expf(lv[k0]);
            cA[k0]  = e0 * inv_s * rsqrtf(2.0f * (float)M_PI * var);
            cB2[k0] = -0.5f * L2E / var;
            mu[k0]  = means[k0];
        }
        if (k1 < K) {
            float var = __expf(lv[k1]);
            cA[k1]  = e1 * inv_s * rsqrtf(2.0f * (float)M_PI * var);
            cB2[k1] = -0.5f * L2E / var;
            mu[k1]  = means[k1];
        }
    }

    gridbar((ep + 2u) * nb);

    // ---- phase 4: windowed KDE + mixture + reduction + replay cleanup ----
    if (t == 0) g_epoch[b] = ep + 2u;
    if (t < NBINS / NB) g_cnt[b * (NBINS / NB) + t] = 0;   // 8 bins/block

    int jl = t / TSUB, ts = t & (TSUB - 1);
    int j  = jl * (int)nb + b;                // strided: balances window sizes

    float kde = 0.0f, mix = 0.0f;
    if (j < n) {
        float xs    = g_xs[j];
        float minS  = RLO * scaleS;
        float invwS = INVW / scaleS;
        const float RS = 6.5f;                // dropped terms < 2^-42

        int lo = min(NBINS - 1, max(0, (int)((xs - RS - minS) * invwS)));
        int hi = min(NBINS - 1, max(0, (int)((xs + RS - minS) * invwS)));
        int i0 = binstart[lo];
        int i1 = binstart[hi + 1];

        float k0 = 0.0f, k1 = 0.0f;
        int i = i0 + ts;
        for (; i + TSUB < i1; i += 2 * TSUB) {
            float d0 = xs - g_xs[i];
            float d1 = xs - g_xs[i + TSUB];
            k0 += ex2f(-d0 * d0);
            k1 += ex2f(-d1 * d1);
        }
        if (i < i1) {
            float d = xs - g_xs[i];
            k0 += ex2f(-d * d);
        }
        kde = k0 + k1;

        float xo = g_xo[j];
        for (int k = ts; k < K; k += TSUB) {
            float d = xo - mu[k];
            mix += cA[k] * ex2f(cB2[k] * d * d);
        }
    }

#pragma unroll
    for (int o = 1; o < TSUB; o <<= 1) {
        kde += __shfl_xor_sync(~0u, kde, o);
        mix += __shfl_xor_sync(~0u, mix, o);
    }

    float val = 0.0f;
    if (j < n && ts == 0) {
        float err = mix - kde * invC;
        val = err * err;
    }
#pragma unroll
    for (int o = 16; o; o >>= 1) val += __shfl_xor_sync(~0u, val, o);
    if (lane == 0) sred[wid] = val;
    __syncthreads();
    if (wid == 0 && lane < 16) {
        float v = sred[lane];
#pragma unroll
        for (int o = 8; o; o >>= 1) v += __shfl_xor_sync(0xffffu, v, o);
        if (lane == 0) atomicAdd(out, v);
    }
}

// ---------------------------------------------------------------------------
extern "C" void kernel_launch(void* const* d_in, const int* in_sizes, int n_in,
                              void* d_out, int out_size) {
    const float* x     = (const float*)d_in[0];
    const float* wl    = (const float*)d_in[1];
    const float* means = (const float*)d_in[2];
    const float* lv    = (const float*)d_in[3];
    float* out = (float*)d_out;

    int n = in_sizes[0];   // 8192
    int K = in_sizes[1];   // 64

    // bandwidth = 0.5 * 128 / n  (= 2^-7 for n = 8192)
    double bw    = 64.0 / (double)n;
    double bw2   = bw * bw;
    double Ckde  = -0.5 / bw2;
    double LOG2E = 1.4426950408889634;
    float  scaleS = (float)sqrt(-Ckde * LOG2E);   // exp2-domain prescale
    float  invC   = (float)(1.0 / (sqrt(2.0 * M_PI * bw2) * (double)n));

    k_fused<<<NB, BLK>>>(x, wl, means, lv, out, n, K, scaleS, invC);
}